// round 2
// baseline (speedup 1.0000x reference)
#include <cuda_runtime.h>

#define NB 16
#define LL 1024
#define DH 256
#define NEGINF (-1e30f)
#define FLT_LOW (-3.4e38f)

typedef unsigned long long u64;

// ---------------- scratch (static device globals; no allocation) -------------
__device__ float g_PW[NB * LL * DH];        // 16 MB   P @ W
__device__ float g_sim[NB * LL * LL];       // 67 MB   bilinear scores (+bias,+mask)
__device__ float g_rowmax[NB * LL];
__device__ float g_rowinv[NB * LL];
__device__ float g_colpart[NB * 8 * LL];    // partial column maxes (8 p-chunks)
__device__ float g_pvec[NB * DH];           // aligned premise vector per batch

// ---------------- packed f32x2 helpers ---------------------------------------
__device__ __forceinline__ void fma2(u64& d, u64 a, u64 b) {
    asm("fma.rn.f32x2 %0, %1, %2, %0;" : "+l"(d) : "l"(a), "l"(b));
}
__device__ __forceinline__ u64 pack2(float x) {
    u64 r;
    asm("mov.b64 %0, {%1, %1};" : "=l"(r) : "f"(x));
    return r;
}
__device__ __forceinline__ float lo32(u64 v) { return __uint_as_float((unsigned)v); }
__device__ __forceinline__ float hi32(u64 v) { return __uint_as_float((unsigned)(v >> 32)); }

// =============================================================================
// Kernel A: g_PW = P(16384x256) @ W(256x256)   (NN)  — f32x2 MACs
// 128x128x8 tile, 256 threads, 8x8 per thread, A duplicated in smem
// =============================================================================
__global__ __launch_bounds__(256, 2) void k_pw(const float* __restrict__ P,
                                               const float* __restrict__ W) {
    __shared__ float As2[8][256];     // duplicated pairs: [k][2r]=[k][2r+1]=A[r][k]
    __shared__ float Bs[8][128];
    const int tid = threadIdx.x;
    const int tx = tid & 15, ty = tid >> 4;
    const int bn = blockIdx.x * 128;
    const int bm = blockIdx.y * 128;
    const int aRow = tid >> 1, aCol = (tid & 1) * 4;
    const int bRow = tid >> 5, bCol = (tid & 31) * 4;
    const float* Ap = P + (size_t)(bm + aRow) * DH + aCol;
    const float* Bp = W + (size_t)bRow * DH + bn + bCol;

    u64 acc[8][4];
#pragma unroll
    for (int i = 0; i < 8; i++)
#pragma unroll
        for (int j = 0; j < 4; j++) acc[i][j] = 0ull;

    for (int k0 = 0; k0 < DH; k0 += 8) {
        float4 av = *(const float4*)(Ap + k0);
        float4 bv = *(const float4*)(Bp + (size_t)k0 * DH);
        ((u64*)As2[aCol + 0])[aRow] = pack2(av.x);
        ((u64*)As2[aCol + 1])[aRow] = pack2(av.y);
        ((u64*)As2[aCol + 2])[aRow] = pack2(av.z);
        ((u64*)As2[aCol + 3])[aRow] = pack2(av.w);
        *(float4*)&Bs[bRow][bCol] = bv;
        __syncthreads();
#pragma unroll
        for (int kk = 0; kk < 8; kk++) {
            ulonglong2 a01 = *(const ulonglong2*)&As2[kk][ty * 16 + 0];
            ulonglong2 a23 = *(const ulonglong2*)&As2[kk][ty * 16 + 4];
            ulonglong2 a45 = *(const ulonglong2*)&As2[kk][ty * 16 + 8];
            ulonglong2 a67 = *(const ulonglong2*)&As2[kk][ty * 16 + 12];
            ulonglong2 bq0 = *(const ulonglong2*)&Bs[kk][tx * 8];
            ulonglong2 bq1 = *(const ulonglong2*)&Bs[kk][tx * 8 + 4];
            u64 ra[8] = {a01.x, a01.y, a23.x, a23.y, a45.x, a45.y, a67.x, a67.y};
            u64 rb[4] = {bq0.x, bq0.y, bq1.x, bq1.y};
#pragma unroll
            for (int i = 0; i < 8; i++)
#pragma unroll
                for (int j = 0; j < 4; j++) fma2(acc[i][j], ra[i], rb[j]);
        }
        __syncthreads();
    }
#pragma unroll
    for (int i = 0; i < 8; i++) {
        int gm = bm + ty * 8 + i;
        float* o = g_PW + (size_t)gm * DH + bn + tx * 8;
        ulonglong2 v0; v0.x = acc[i][0]; v0.y = acc[i][1];
        ulonglong2 v1; v1.x = acc[i][2]; v1.y = acc[i][3];
        *(ulonglong2*)(o)     = v0;
        *(ulonglong2*)(o + 4) = v1;
    }
}

// =============================================================================
// Kernel B: g_sim[b] = g_PW[b] @ H[b]^T + bias + mask   (NT, per batch) f32x2
// =============================================================================
__global__ __launch_bounds__(256, 2) void k_sim(const float* __restrict__ Hh,
                                                const int* __restrict__ pmask,
                                                const int* __restrict__ hmask,
                                                const float* __restrict__ bias) {
    __shared__ float As2[8][256];
    __shared__ float Bs[8][128];
    const int b = blockIdx.z;
    const int tid = threadIdx.x;
    const int tx = tid & 15, ty = tid >> 4;
    const int bn = blockIdx.x * 128;
    const int bm = blockIdx.y * 128;
    const int r = tid >> 1, c4 = (tid & 1) * 4;
    const float* Ap = g_PW + (size_t)b * LL * DH + (size_t)(bm + r) * DH + c4;
    const float* Bp = Hh   + (size_t)b * LL * DH + (size_t)(bn + r) * DH + c4;

    u64 acc[8][4];
#pragma unroll
    for (int i = 0; i < 8; i++)
#pragma unroll
        for (int j = 0; j < 4; j++) acc[i][j] = 0ull;

    for (int k0 = 0; k0 < DH; k0 += 8) {
        float4 av = *(const float4*)(Ap + k0);
        float4 bv = *(const float4*)(Bp + k0);
        ((u64*)As2[c4 + 0])[r] = pack2(av.x);
        ((u64*)As2[c4 + 1])[r] = pack2(av.y);
        ((u64*)As2[c4 + 2])[r] = pack2(av.z);
        ((u64*)As2[c4 + 3])[r] = pack2(av.w);
        Bs[c4 + 0][r] = bv.x; Bs[c4 + 1][r] = bv.y;
        Bs[c4 + 2][r] = bv.z; Bs[c4 + 3][r] = bv.w;
        __syncthreads();
#pragma unroll
        for (int kk = 0; kk < 8; kk++) {
            ulonglong2 a01 = *(const ulonglong2*)&As2[kk][ty * 16 + 0];
            ulonglong2 a23 = *(const ulonglong2*)&As2[kk][ty * 16 + 4];
            ulonglong2 a45 = *(const ulonglong2*)&As2[kk][ty * 16 + 8];
            ulonglong2 a67 = *(const ulonglong2*)&As2[kk][ty * 16 + 12];
            ulonglong2 bq0 = *(const ulonglong2*)&Bs[kk][tx * 8];
            ulonglong2 bq1 = *(const ulonglong2*)&Bs[kk][tx * 8 + 4];
            u64 ra[8] = {a01.x, a01.y, a23.x, a23.y, a45.x, a45.y, a67.x, a67.y};
            u64 rb[4] = {bq0.x, bq0.y, bq1.x, bq1.y};
#pragma unroll
            for (int i = 0; i < 8; i++)
#pragma unroll
                for (int j = 0; j < 4; j++) fma2(acc[i][j], ra[i], rb[j]);
        }
        __syncthreads();
    }

    const float bb = bias[0];
    float pmv[8], hmv[8];
#pragma unroll
    for (int i = 0; i < 8; i++) pmv[i] = (float)pmask[b * LL + bm + ty * 8 + i];
#pragma unroll
    for (int j = 0; j < 8; j++) hmv[j] = (float)hmask[b * LL + bn + tx * 8 + j];

#pragma unroll
    for (int i = 0; i < 8; i++) {
        int gm = bm + ty * 8 + i;
        float v[8];
#pragma unroll
        for (int j = 0; j < 4; j++) {
            v[2 * j]     = lo32(acc[i][j]);
            v[2 * j + 1] = hi32(acc[i][j]);
        }
#pragma unroll
        for (int j = 0; j < 8; j++)
            v[j] = v[j] + bb + (1.0f - pmv[i] * hmv[j]) * NEGINF;
        float* o = g_sim + ((size_t)b * LL + gm) * LL + bn + tx * 8;
        *(float4*)(o)     = make_float4(v[0], v[1], v[2], v[3]);
        *(float4*)(o + 4) = make_float4(v[4], v[5], v[6], v[7]);
    }
}

// =============================================================================
// Kernel C: per-row max & 1/sum(exp)  (one block of 128 threads per row)
// =============================================================================
__global__ void k_rowstats() {
    const int row = blockIdx.x;             // b*LL + p
    const float* s = g_sim + (size_t)row * LL;
    const int t = threadIdx.x;
    float4 v0 = *(const float4*)(s + t * 8);
    float4 v1 = *(const float4*)(s + t * 8 + 4);
    float m = fmaxf(fmaxf(fmaxf(v0.x, v0.y), fmaxf(v0.z, v0.w)),
                    fmaxf(fmaxf(v1.x, v1.y), fmaxf(v1.z, v1.w)));
#pragma unroll
    for (int o = 16; o > 0; o >>= 1) m = fmaxf(m, __shfl_xor_sync(0xffffffffu, m, o));
    __shared__ float sm[4], ss[4];
    const int w = t >> 5, lane = t & 31;
    if (lane == 0) sm[w] = m;
    __syncthreads();
    m = fmaxf(fmaxf(sm[0], sm[1]), fmaxf(sm[2], sm[3]));
    float sum = __expf(v0.x - m) + __expf(v0.y - m) + __expf(v0.z - m) + __expf(v0.w - m)
              + __expf(v1.x - m) + __expf(v1.y - m) + __expf(v1.z - m) + __expf(v1.w - m);
#pragma unroll
    for (int o = 16; o > 0; o >>= 1) sum += __shfl_xor_sync(0xffffffffu, sum, o);
    if (lane == 0) ss[w] = sum;
    __syncthreads();
    if (t == 0) {
        g_rowmax[row] = m;
        g_rowinv[row] = 1.0f / (ss[0] + ss[1] + ss[2] + ss[3]);
    }
}

// =============================================================================
// Kernel C2: partial column maxes (grid: qchunk=4, pchunk=8, batch)
// =============================================================================
__global__ void k_colmax() {
    const int b = blockIdx.z;
    const int q = blockIdx.x * 256 + threadIdx.x;
    const int p0 = blockIdx.y * 128;
    const float* s = g_sim + ((size_t)b * LL + p0) * LL + q;
    float m = FLT_LOW;
#pragma unroll 8
    for (int p = 0; p < 128; p++) m = fmaxf(m, s[(size_t)p * LL]);
    g_colpart[((size_t)b * 8 + blockIdx.y) * LL + q] = m;
}

// =============================================================================
// Kernel D: aligned_hyp[b] = softmax(sim[b]) @ H[b]   (NN, on-the-fly) f32x2
// =============================================================================
__global__ __launch_bounds__(256, 2) void k_av(const float* __restrict__ Hh,
                                               float* __restrict__ out) {
    __shared__ float As2[8][256];
    __shared__ float Bs[8][128];
    const int b = blockIdx.z;
    const int tid = threadIdx.x;
    const int tx = tid & 15, ty = tid >> 4;
    const int bn = blockIdx.x * 128;     // over DH (2 tiles)
    const int bm = blockIdx.y * 128;     // over rows
    const int aRow = tid >> 1, aCol = (tid & 1) * 4;
    const int bRow = tid >> 5, bCol = (tid & 31) * 4;
    const int grow = bm + aRow;
    const float rm = g_rowmax[b * LL + grow];
    const float ri = g_rowinv[b * LL + grow];
    const float* Ap = g_sim + ((size_t)b * LL + grow) * LL + aCol;
    const float* Bp = Hh + (size_t)b * LL * DH + (size_t)bRow * DH + bn + bCol;

    u64 acc[8][4];
#pragma unroll
    for (int i = 0; i < 8; i++)
#pragma unroll
        for (int j = 0; j < 4; j++) acc[i][j] = 0ull;

    for (int k0 = 0; k0 < LL; k0 += 8) {
        float4 av = *(const float4*)(Ap + k0);
        av.x = __expf(av.x - rm) * ri;
        av.y = __expf(av.y - rm) * ri;
        av.z = __expf(av.z - rm) * ri;
        av.w = __expf(av.w - rm) * ri;
        float4 bv = *(const float4*)(Bp + (size_t)k0 * DH);
        ((u64*)As2[aCol + 0])[aRow] = pack2(av.x);
        ((u64*)As2[aCol + 1])[aRow] = pack2(av.y);
        ((u64*)As2[aCol + 2])[aRow] = pack2(av.z);
        ((u64*)As2[aCol + 3])[aRow] = pack2(av.w);
        *(float4*)&Bs[bRow][bCol] = bv;
        __syncthreads();
#pragma unroll
        for (int kk = 0; kk < 8; kk++) {
            ulonglong2 a01 = *(const ulonglong2*)&As2[kk][ty * 16 + 0];
            ulonglong2 a23 = *(const ulonglong2*)&As2[kk][ty * 16 + 4];
            ulonglong2 a45 = *(const ulonglong2*)&As2[kk][ty * 16 + 8];
            ulonglong2 a67 = *(const ulonglong2*)&As2[kk][ty * 16 + 12];
            ulonglong2 bq0 = *(const ulonglong2*)&Bs[kk][tx * 8];
            ulonglong2 bq1 = *(const ulonglong2*)&Bs[kk][tx * 8 + 4];
            u64 ra[8] = {a01.x, a01.y, a23.x, a23.y, a45.x, a45.y, a67.x, a67.y};
            u64 rb[4] = {bq0.x, bq0.y, bq1.x, bq1.y};
#pragma unroll
            for (int i = 0; i < 8; i++)
#pragma unroll
                for (int j = 0; j < 4; j++) fma2(acc[i][j], ra[i], rb[j]);
        }
        __syncthreads();
    }
#pragma unroll
    for (int i = 0; i < 8; i++) {
        int gm = bm + ty * 8 + i;
        float* o = out + (size_t)b * LL * DH + (size_t)gm * DH + bn + tx * 8;
        ulonglong2 v0; v0.x = acc[i][0]; v0.y = acc[i][1];
        ulonglong2 v1; v1.x = acc[i][2]; v1.y = acc[i][3];
        *(ulonglong2*)(o)     = v0;
        *(ulonglong2*)(o + 4) = v1;
    }
}

// =============================================================================
// Kernel E: per batch — softmax(colmax) @ P -> g_pvec[b, 256]
// =============================================================================
__global__ __launch_bounds__(256) void k_premise(const float* __restrict__ P) {
    const int b = blockIdx.x;
    const int t = threadIdx.x;
    __shared__ float prob[LL];
    __shared__ float red[8];
    float loc[4];
#pragma unroll
    for (int c = 0; c < 4; c++) {
        int q = c * 256 + t;
        float m = FLT_LOW;
#pragma unroll
        for (int j = 0; j < 8; j++)
            m = fmaxf(m, g_colpart[((size_t)b * 8 + j) * LL + q]);
        loc[c] = m;
    }
    float mx = fmaxf(fmaxf(loc[0], loc[1]), fmaxf(loc[2], loc[3]));
#pragma unroll
    for (int o = 16; o > 0; o >>= 1) mx = fmaxf(mx, __shfl_xor_sync(0xffffffffu, mx, o));
    const int w = t >> 5, lane = t & 31;
    if (lane == 0) red[w] = mx;
    __syncthreads();
    mx = red[0];
#pragma unroll
    for (int j = 1; j < 8; j++) mx = fmaxf(mx, red[j]);

    float se = 0.0f;
#pragma unroll
    for (int c = 0; c < 4; c++) {
        float e = __expf(loc[c] - mx);
        prob[c * 256 + t] = e;
        se += e;
    }
#pragma unroll
    for (int o = 16; o > 0; o >>= 1) se += __shfl_xor_sync(0xffffffffu, se, o);
    __syncthreads();               // red reads done before reuse
    if (lane == 0) red[w] = se;
    __syncthreads();
    float tot = 0.0f;
#pragma unroll
    for (int j = 0; j < 8; j++) tot += red[j];
    const float inv = 1.0f / tot;

    const float* Pb = P + (size_t)b * LL * DH + t;   // thread t owns dim d=t
    float acc = 0.0f;
#pragma unroll 8
    for (int q = 0; q < LL; q++)
        acc = fmaf(prob[q], Pb[(size_t)q * DH], acc);
    g_pvec[b * DH + t] = acc * inv;
}

// =============================================================================
// Kernel F: broadcast g_pvec -> out[0 : NB*LL*DH)
// =============================================================================
__global__ void k_bcast(float* __restrict__ out) {
    int idx = (blockIdx.x * 256 + threadIdx.x) * 4;   // < 4194304
    int b = idx >> 18;           // LL*DH = 2^18
    int d = idx & (DH - 1);
    float4 v = *(const float4*)&g_pvec[b * DH + d];
    *(float4*)&out[idx] = v;
}

// =============================================================================
extern "C" void kernel_launch(void* const* d_in, const int* in_sizes, int n_in,
                              void* d_out, int out_size) {
    const float* P    = (const float*)d_in[0];
    const float* Hh   = (const float*)d_in[1];
    const int*   pm   = (const int*)d_in[2];
    const int*   hm   = (const int*)d_in[3];
    const float* W    = (const float*)d_in[4];
    const float* bias = (const float*)d_in[5];
    float* out = (float*)d_out;

    k_pw      <<<dim3(DH / 128, (NB * LL) / 128), 256>>>(P, W);
    k_sim     <<<dim3(LL / 128, LL / 128, NB), 256>>>(Hh, pm, hm, bias);
    k_rowstats<<<NB * LL, 128>>>();
    k_colmax  <<<dim3(LL / 256, 8, NB), 256>>>();
    k_av      <<<dim3(DH / 128, LL / 128, NB), 256>>>(Hh, out + (size_t)NB * LL * DH);
    k_premise <<<NB, 256>>>(P);
    k_bcast   <<<(NB * LL * DH) / (256 * 4), 256>>>(out);
}

// round 3
// speedup vs baseline: 1.7660x; 1.7660x over previous
#include <cuda_runtime.h>
#include <cuda_bf16.h>

#define NB 16
#define LL 1024
#define DH 256
#define NEGINF (-1e30f)
#define FLT_LOW (-3.4e38f)

// ---------------- scratch (static device globals; no allocation) -------------
__device__ float g_sim[NB * LL * LL];                 // 67 MB scores
__device__ __nv_bfloat16 g_PWhi[NB * LL * DH];        // P@W split
__device__ __nv_bfloat16 g_PWlo[NB * LL * DH];
__device__ __nv_bfloat16 g_Hhi[NB * LL * DH];         // H split
__device__ __nv_bfloat16 g_Hlo[NB * LL * DH];
__device__ float g_rowmax[NB * LL];
__device__ float g_rowinv[NB * LL];
__device__ float g_colpart[NB * 8 * LL];
__device__ float g_pvec[NB * DH];

union BF8 { uint4 v; __nv_bfloat16 h[8]; };
union BF4 { uint2 v; __nv_bfloat16 h[4]; };

__device__ __forceinline__ void mma_bf16(float d[4], const unsigned a[4], const unsigned b[2]) {
    asm volatile(
        "mma.sync.aligned.m16n8k16.row.col.f32.bf16.bf16.f32 "
        "{%0,%1,%2,%3}, {%4,%5,%6,%7}, {%8,%9}, {%0,%1,%2,%3};"
        : "+f"(d[0]), "+f"(d[1]), "+f"(d[2]), "+f"(d[3])
        : "r"(a[0]), "r"(a[1]), "r"(a[2]), "r"(a[3]), "r"(b[0]), "r"(b[1]));
}

__device__ __forceinline__ void split_bf16(float f, __nv_bfloat16& hi, __nv_bfloat16& lo) {
    hi = __float2bfloat16(f);
    lo = __float2bfloat16(f - __bfloat162float(hi));
}

// =============================================================================
// Kernel CVT: H fp32 -> hi/lo bf16
// =============================================================================
__global__ void k_cvt(const float* __restrict__ X) {
    size_t i = ((size_t)blockIdx.x * 256 + threadIdx.x) * 4;
    float4 v = *(const float4*)(X + i);
    BF4 hi, lo;
    split_bf16(v.x, hi.h[0], lo.h[0]);
    split_bf16(v.y, hi.h[1], lo.h[1]);
    split_bf16(v.z, hi.h[2], lo.h[2]);
    split_bf16(v.w, hi.h[3], lo.h[3]);
    *(uint2*)&g_Hhi[i] = hi.v;
    *(uint2*)&g_Hlo[i] = lo.v;
}

// =============================================================================
// Kernel A: PW = P @ W (fp32 FFMA, 128x128x8) -> writes split bf16
// =============================================================================
__global__ __launch_bounds__(256, 2) void k_pw(const float* __restrict__ P,
                                               const float* __restrict__ W) {
    __shared__ float As[8][128];
    __shared__ float Bs[8][128];
    const int tid = threadIdx.x;
    const int tx = tid & 15, ty = tid >> 4;
    const int bn = blockIdx.x * 128;
    const int bm = blockIdx.y * 128;
    const int aRow = tid >> 1, aCol = (tid & 1) * 4;
    const int bRow = tid >> 5, bCol = (tid & 31) * 4;
    const float* Ap = P + (size_t)(bm + aRow) * DH + aCol;
    const float* Bp = W + (size_t)bRow * DH + bn + bCol;

    float acc[8][8];
#pragma unroll
    for (int i = 0; i < 8; i++)
#pragma unroll
        for (int j = 0; j < 8; j++) acc[i][j] = 0.0f;

    for (int k0 = 0; k0 < DH; k0 += 8) {
        float4 av = *(const float4*)(Ap + k0);
        float4 bv = *(const float4*)(Bp + (size_t)k0 * DH);
        As[aCol + 0][aRow] = av.x; As[aCol + 1][aRow] = av.y;
        As[aCol + 2][aRow] = av.z; As[aCol + 3][aRow] = av.w;
        *(float4*)&Bs[bRow][bCol] = bv;
        __syncthreads();
#pragma unroll
        for (int kk = 0; kk < 8; kk++) {
            float4 a0 = *(const float4*)&As[kk][ty * 8];
            float4 a1 = *(const float4*)&As[kk][ty * 8 + 4];
            float4 b0 = *(const float4*)&Bs[kk][tx * 8];
            float4 b1 = *(const float4*)&Bs[kk][tx * 8 + 4];
            float ra[8] = {a0.x, a0.y, a0.z, a0.w, a1.x, a1.y, a1.z, a1.w};
            float rb[8] = {b0.x, b0.y, b0.z, b0.w, b1.x, b1.y, b1.z, b1.w};
#pragma unroll
            for (int i = 0; i < 8; i++)
#pragma unroll
                for (int j = 0; j < 8; j++)
                    acc[i][j] = fmaf(ra[i], rb[j], acc[i][j]);
        }
        __syncthreads();
    }
#pragma unroll
    for (int i = 0; i < 8; i++) {
        int gm = bm + ty * 8 + i;
        BF8 hi, lo;
#pragma unroll
        for (int j = 0; j < 8; j++) split_bf16(acc[i][j], hi.h[j], lo.h[j]);
        size_t o = (size_t)gm * DH + bn + tx * 8;
        *(uint4*)&g_PWhi[o] = hi.v;
        *(uint4*)&g_PWlo[o] = lo.v;
    }
}

// =============================================================================
// Kernel B: sim[b] = PW[b] @ H[b]^T + bias + mask  — tensor-core split-bf16
// block 256 thr (8 warps), tile 128x128, warp 64x32, KC=32
// =============================================================================
__global__ __launch_bounds__(256) void k_sim(const int* __restrict__ pmask,
                                             const int* __restrict__ hmask,
                                             const float* __restrict__ bias) {
    __shared__ __align__(16) __nv_bfloat16 Ah[128][40], Al[128][40];
    __shared__ __align__(16) __nv_bfloat16 Bh[128][40], Bl[128][40];
    const int b = blockIdx.z;
    const int bm = blockIdx.y * 128, bn = blockIdx.x * 128;
    const int tid = threadIdx.x, warp = tid >> 5, lane = tid & 31;
    const int wm = (warp >> 2) * 64, wn = (warp & 3) * 32;
    const int gid = lane >> 2, tig = lane & 3;
    const int lrow = tid >> 1, lseg = (tid & 1) * 16;

    const size_t abase = ((size_t)b * LL + bm + lrow) * DH + lseg;
    const size_t bbase = ((size_t)b * LL + bn + lrow) * DH + lseg;

    float acc[4][4][4];
#pragma unroll
    for (int mt = 0; mt < 4; mt++)
#pragma unroll
        for (int nt = 0; nt < 4; nt++)
#pragma unroll
            for (int e = 0; e < 4; e++) acc[mt][nt][e] = 0.0f;

    for (int k0 = 0; k0 < DH; k0 += 32) {
        uint4 ah0 = *(const uint4*)&g_PWhi[abase + k0];
        uint4 ah1 = *(const uint4*)&g_PWhi[abase + k0 + 8];
        uint4 al0 = *(const uint4*)&g_PWlo[abase + k0];
        uint4 al1 = *(const uint4*)&g_PWlo[abase + k0 + 8];
        uint4 bh0 = *(const uint4*)&g_Hhi[bbase + k0];
        uint4 bh1 = *(const uint4*)&g_Hhi[bbase + k0 + 8];
        uint4 bl0 = *(const uint4*)&g_Hlo[bbase + k0];
        uint4 bl1 = *(const uint4*)&g_Hlo[bbase + k0 + 8];
        __syncthreads();
        *(uint4*)&Ah[lrow][lseg] = ah0; *(uint4*)&Ah[lrow][lseg + 8] = ah1;
        *(uint4*)&Al[lrow][lseg] = al0; *(uint4*)&Al[lrow][lseg + 8] = al1;
        *(uint4*)&Bh[lrow][lseg] = bh0; *(uint4*)&Bh[lrow][lseg + 8] = bh1;
        *(uint4*)&Bl[lrow][lseg] = bl0; *(uint4*)&Bl[lrow][lseg + 8] = bl1;
        __syncthreads();
#pragma unroll
        for (int ks = 0; ks < 32; ks += 16) {
            unsigned afh[4][4], afl[4][4];
#pragma unroll
            for (int mt = 0; mt < 4; mt++) {
                int r = wm + mt * 16 + gid;
                afh[mt][0] = *(const unsigned*)&Ah[r][ks + tig * 2];
                afh[mt][1] = *(const unsigned*)&Ah[r + 8][ks + tig * 2];
                afh[mt][2] = *(const unsigned*)&Ah[r][ks + tig * 2 + 8];
                afh[mt][3] = *(const unsigned*)&Ah[r + 8][ks + tig * 2 + 8];
                afl[mt][0] = *(const unsigned*)&Al[r][ks + tig * 2];
                afl[mt][1] = *(const unsigned*)&Al[r + 8][ks + tig * 2];
                afl[mt][2] = *(const unsigned*)&Al[r][ks + tig * 2 + 8];
                afl[mt][3] = *(const unsigned*)&Al[r + 8][ks + tig * 2 + 8];
            }
#pragma unroll
            for (int nt = 0; nt < 4; nt++) {
                int nr = wn + nt * 8 + gid;
                unsigned bfh[2] = {*(const unsigned*)&Bh[nr][ks + tig * 2],
                                   *(const unsigned*)&Bh[nr][ks + tig * 2 + 8]};
                unsigned bfl[2] = {*(const unsigned*)&Bl[nr][ks + tig * 2],
                                   *(const unsigned*)&Bl[nr][ks + tig * 2 + 8]};
#pragma unroll
                for (int mt = 0; mt < 4; mt++) {
                    mma_bf16(acc[mt][nt], afh[mt], bfh);
                    mma_bf16(acc[mt][nt], afh[mt], bfl);
                    mma_bf16(acc[mt][nt], afl[mt], bfh);
                }
            }
        }
    }

    const float bb = bias[0];
#pragma unroll
    for (int mt = 0; mt < 4; mt++) {
        int r0 = bm + wm + mt * 16 + gid, r1 = r0 + 8;
        float pm0 = (float)pmask[b * LL + r0];
        float pm1 = (float)pmask[b * LL + r1];
#pragma unroll
        for (int nt = 0; nt < 4; nt++) {
            int c = bn + wn + nt * 8 + tig * 2;
            float hm0 = (float)hmask[b * LL + c];
            float hm1 = (float)hmask[b * LL + c + 1];
            float* d = acc[mt][nt];
            float2 v0 = make_float2(d[0] + bb + (1.0f - pm0 * hm0) * NEGINF,
                                    d[1] + bb + (1.0f - pm0 * hm1) * NEGINF);
            float2 v1 = make_float2(d[2] + bb + (1.0f - pm1 * hm0) * NEGINF,
                                    d[3] + bb + (1.0f - pm1 * hm1) * NEGINF);
            *(float2*)&g_sim[((size_t)b * LL + r0) * LL + c] = v0;
            *(float2*)&g_sim[((size_t)b * LL + r1) * LL + c] = v1;
        }
    }
}

// =============================================================================
// Kernel C: per-row max & 1/sum(exp)
// =============================================================================
__global__ void k_rowstats() {
    const int row = blockIdx.x;
    const float* s = g_sim + (size_t)row * LL;
    const int t = threadIdx.x;
    float4 v0 = *(const float4*)(s + t * 8);
    float4 v1 = *(const float4*)(s + t * 8 + 4);
    float m = fmaxf(fmaxf(fmaxf(v0.x, v0.y), fmaxf(v0.z, v0.w)),
                    fmaxf(fmaxf(v1.x, v1.y), fmaxf(v1.z, v1.w)));
#pragma unroll
    for (int o = 16; o > 0; o >>= 1) m = fmaxf(m, __shfl_xor_sync(0xffffffffu, m, o));
    __shared__ float sm[4], ss[4];
    const int w = t >> 5, lane = t & 31;
    if (lane == 0) sm[w] = m;
    __syncthreads();
    m = fmaxf(fmaxf(sm[0], sm[1]), fmaxf(sm[2], sm[3]));
    float sum = __expf(v0.x - m) + __expf(v0.y - m) + __expf(v0.z - m) + __expf(v0.w - m)
              + __expf(v1.x - m) + __expf(v1.y - m) + __expf(v1.z - m) + __expf(v1.w - m);
#pragma unroll
    for (int o = 16; o > 0; o >>= 1) sum += __shfl_xor_sync(0xffffffffu, sum, o);
    if (lane == 0) ss[w] = sum;
    __syncthreads();
    if (t == 0) {
        g_rowmax[row] = m;
        g_rowinv[row] = 1.0f / (ss[0] + ss[1] + ss[2] + ss[3]);
    }
}

// =============================================================================
// Kernel C2: partial column maxes
// =============================================================================
__global__ void k_colmax() {
    const int b = blockIdx.z;
    const int q = blockIdx.x * 256 + threadIdx.x;
    const int p0 = blockIdx.y * 128;
    const float* s = g_sim + ((size_t)b * LL + p0) * LL + q;
    float m = FLT_LOW;
#pragma unroll 8
    for (int p = 0; p < 128; p++) m = fmaxf(m, s[(size_t)p * LL]);
    g_colpart[((size_t)b * 8 + blockIdx.y) * LL + q] = m;
}

// =============================================================================
// Kernel D: aligned_hyp[b] = softmax(sim[b]) @ H[b] — tensor-core split-bf16
// A = exp(sim-rm)*ri computed on the fly; B = H transposed in smem
// =============================================================================
__global__ __launch_bounds__(256) void k_av(float* __restrict__ out) {
    __shared__ __align__(16) __nv_bfloat16 Ah[128][40], Al[128][40];
    __shared__ __align__(16) __nv_bfloat16 Bh[128][40], Bl[128][40];
    const int b = blockIdx.z;
    const int bm = blockIdx.y * 128, bn = blockIdx.x * 128;   // bn over DH
    const int tid = threadIdx.x, warp = tid >> 5, lane = tid & 31;
    const int wm = (warp >> 2) * 64, wn = (warp & 3) * 32;
    const int gid = lane >> 2, tig = lane & 3;
    const int lrow = tid >> 1, lseg = (tid & 1) * 16;
    const int qloc = tid & 31, dbase = (tid >> 5) * 16;

    const float rm = g_rowmax[b * LL + bm + lrow];
    const float ri = g_rowinv[b * LL + bm + lrow];
    const float* sp = &g_sim[((size_t)b * LL + bm + lrow) * LL + lseg];

    float acc[4][4][4];
#pragma unroll
    for (int mt = 0; mt < 4; mt++)
#pragma unroll
        for (int nt = 0; nt < 4; nt++)
#pragma unroll
            for (int e = 0; e < 4; e++) acc[mt][nt][e] = 0.0f;

    for (int k0 = 0; k0 < LL; k0 += 32) {
        float4 f0 = *(const float4*)(sp + k0);
        float4 f1 = *(const float4*)(sp + k0 + 4);
        float4 f2 = *(const float4*)(sp + k0 + 8);
        float4 f3 = *(const float4*)(sp + k0 + 12);
        size_t hb = ((size_t)b * LL + k0 + qloc) * DH + bn + dbase;
        BF8 hh0 = *(const BF8*)&g_Hhi[hb];
        BF8 hh1 = *(const BF8*)&g_Hhi[hb + 8];
        BF8 hl0 = *(const BF8*)&g_Hlo[hb];
        BF8 hl1 = *(const BF8*)&g_Hlo[hb + 8];
        __syncthreads();
        {
            float e[16] = {f0.x, f0.y, f0.z, f0.w, f1.x, f1.y, f1.z, f1.w,
                           f2.x, f2.y, f2.z, f2.w, f3.x, f3.y, f3.z, f3.w};
            BF8 phi0, phi1, plo0, plo1;
#pragma unroll
            for (int i = 0; i < 8; i++) {
                float p0 = __expf(e[i] - rm) * ri;
                float p1 = __expf(e[8 + i] - rm) * ri;
                split_bf16(p0, phi0.h[i], plo0.h[i]);
                split_bf16(p1, phi1.h[i], plo1.h[i]);
            }
            *(uint4*)&Ah[lrow][lseg] = phi0.v; *(uint4*)&Ah[lrow][lseg + 8] = phi1.v;
            *(uint4*)&Al[lrow][lseg] = plo0.v; *(uint4*)&Al[lrow][lseg + 8] = plo1.v;
        }
#pragma unroll
        for (int i = 0; i < 8; i++) {
            Bh[dbase + i][qloc] = hh0.h[i];
            Bh[dbase + 8 + i][qloc] = hh1.h[i];
            Bl[dbase + i][qloc] = hl0.h[i];
            Bl[dbase + 8 + i][qloc] = hl1.h[i];
        }
        __syncthreads();
#pragma unroll
        for (int ks = 0; ks < 32; ks += 16) {
            unsigned afh[4][4], afl[4][4];
#pragma unroll
            for (int mt = 0; mt < 4; mt++) {
                int r = wm + mt * 16 + gid;
                afh[mt][0] = *(const unsigned*)&Ah[r][ks + tig * 2];
                afh[mt][1] = *(const unsigned*)&Ah[r + 8][ks + tig * 2];
                afh[mt][2] = *(const unsigned*)&Ah[r][ks + tig * 2 + 8];
                afh[mt][3] = *(const unsigned*)&Ah[r + 8][ks + tig * 2 + 8];
                afl[mt][0] = *(const unsigned*)&Al[r][ks + tig * 2];
                afl[mt][1] = *(const unsigned*)&Al[r + 8][ks + tig * 2];
                afl[mt][2] = *(const unsigned*)&Al[r][ks + tig * 2 + 8];
                afl[mt][3] = *(const unsigned*)&Al[r + 8][ks + tig * 2 + 8];
            }
#pragma unroll
            for (int nt = 0; nt < 4; nt++) {
                int nr = wn + nt * 8 + gid;
                unsigned bfh[2] = {*(const unsigned*)&Bh[nr][ks + tig * 2],
                                   *(const unsigned*)&Bh[nr][ks + tig * 2 + 8]};
                unsigned bfl[2] = {*(const unsigned*)&Bl[nr][ks + tig * 2],
                                   *(const unsigned*)&Bl[nr][ks + tig * 2 + 8]};
#pragma unroll
                for (int mt = 0; mt < 4; mt++) {
                    mma_bf16(acc[mt][nt], afh[mt], bfh);
                    mma_bf16(acc[mt][nt], afh[mt], bfl);
                    mma_bf16(acc[mt][nt], afl[mt], bfh);
                }
            }
        }
    }
#pragma unroll
    for (int mt = 0; mt < 4; mt++) {
        int r0 = bm + wm + mt * 16 + gid, r1 = r0 + 8;
#pragma unroll
        for (int nt = 0; nt < 4; nt++) {
            int c = bn + wn + nt * 8 + tig * 2;
            float* d = acc[mt][nt];
            *(float2*)&out[((size_t)b * LL + r0) * DH + c] = make_float2(d[0], d[1]);
            *(float2*)&out[((size_t)b * LL + r1) * DH + c] = make_float2(d[2], d[3]);
        }
    }
}

// =============================================================================
// Kernel E: per batch — softmax(colmax) @ P -> g_pvec[b, 256]
// =============================================================================
__global__ __launch_bounds__(256) void k_premise(const float* __restrict__ P) {
    const int b = blockIdx.x;
    const int t = threadIdx.x;
    __shared__ float prob[LL];
    __shared__ float red[8];
    float loc[4];
#pragma unroll
    for (int c = 0; c < 4; c++) {
        int q = c * 256 + t;
        float m = FLT_LOW;
#pragma unroll
        for (int j = 0; j < 8; j++)
            m = fmaxf(m, g_colpart[((size_t)b * 8 + j) * LL + q]);
        loc[c] = m;
    }
    float mx = fmaxf(fmaxf(loc[0], loc[1]), fmaxf(loc[2], loc[3]));
#pragma unroll
    for (int o = 16; o > 0; o >>= 1) mx = fmaxf(mx, __shfl_xor_sync(0xffffffffu, mx, o));
    const int w = t >> 5, lane = t & 31;
    if (lane == 0) red[w] = mx;
    __syncthreads();
    mx = red[0];
#pragma unroll
    for (int j = 1; j < 8; j++) mx = fmaxf(mx, red[j]);

    float se = 0.0f;
#pragma unroll
    for (int c = 0; c < 4; c++) {
        float e = __expf(loc[c] - mx);
        prob[c * 256 + t] = e;
        se += e;
    }
#pragma unroll
    for (int o = 16; o > 0; o >>= 1) se += __shfl_xor_sync(0xffffffffu, se, o);
    __syncthreads();
    if (lane == 0) red[w] = se;
    __syncthreads();
    float tot = 0.0f;
#pragma unroll
    for (int j = 0; j < 8; j++) tot += red[j];
    const float inv = 1.0f / tot;

    const float* Pb = P + (size_t)b * LL * DH + t;
    float acc = 0.0f;
#pragma unroll 8
    for (int q = 0; q < LL; q++)
        acc = fmaf(prob[q], Pb[(size_t)q * DH], acc);
    g_pvec[b * DH + t] = acc * inv;
}

// =============================================================================
// Kernel F: broadcast g_pvec -> out[0 : NB*LL*DH)
// =============================================================================
__global__ void k_bcast(float* __restrict__ out) {
    int idx = (blockIdx.x * 256 + threadIdx.x) * 4;
    int b = idx >> 18;
    int d = idx & (DH - 1);
    float4 v = *(const float4*)&g_pvec[b * DH + d];
    *(float4*)&out[idx] = v;
}

// =============================================================================
extern "C" void kernel_launch(void* const* d_in, const int* in_sizes, int n_in,
                              void* d_out, int out_size) {
    const float* P    = (const float*)d_in[0];
    const float* Hh   = (const float*)d_in[1];
    const int*   pm   = (const int*)d_in[2];
    const int*   hm   = (const int*)d_in[3];
    const float* W    = (const float*)d_in[4];
    const float* bias = (const float*)d_in[5];
    float* out = (float*)d_out;

    k_cvt     <<<(NB * LL * DH) / (256 * 4), 256>>>(Hh);
    k_pw      <<<dim3(DH / 128, (NB * LL) / 128), 256>>>(P, W);
    k_sim     <<<dim3(LL / 128, LL / 128, NB), 256>>>(pm, hm, bias);
    k_rowstats<<<NB * LL, 128>>>();
    k_colmax  <<<dim3(LL / 256, 8, NB), 256>>>();
    k_av      <<<dim3(DH / 128, LL / 128, NB), 256>>>(out + (size_t)NB * LL * DH);
    k_premise <<<NB, 256>>>(P);
    k_bcast   <<<(NB * LL * DH) / (256 * 4), 256>>>(out);
}

// round 8
// speedup vs baseline: 1.7684x; 1.0014x over previous
#include <cuda_runtime.h>
#include <cuda_bf16.h>

#define NB 16
#define LL 1024
#define DH 256
#define NEGINF (-1e30f)
#define FLT_LOW (-3.4e38f)

// ---------------- scratch (static device globals; no allocation) -------------
__device__ float g_sim[NB * LL * LL];                 // 67 MB scores
__device__ __nv_bfloat16 g_PWhi[NB * LL * DH];
__device__ __nv_bfloat16 g_PWlo[NB * LL * DH];
__device__ __nv_bfloat16 g_Hhi[NB * LL * DH];
__device__ __nv_bfloat16 g_Hlo[NB * LL * DH];
__device__ __nv_bfloat16 g_Phi[NB * LL * DH];
__device__ __nv_bfloat16 g_Plo[NB * LL * DH];
__device__ __nv_bfloat16 g_Wthi[DH * DH];             // W^T split: [e][d]
__device__ __nv_bfloat16 g_Wtlo[DH * DH];
__device__ float g_rowmax[NB * LL];
__device__ float g_rowinv[NB * LL];
__device__ float g_colpart[NB * 64 * LL];             // 64 p-chunks per batch
__device__ float g_pvec[NB * DH];

union BF8 { uint4 v; __nv_bfloat16 h[8]; };
union BF4 { uint2 v; __nv_bfloat16 h[4]; };
union BF2 { unsigned u; __nv_bfloat16 h[2]; };

__device__ __forceinline__ void mma_bf16(float d[4], const unsigned a[4], const unsigned b[2]) {
    asm volatile(
        "mma.sync.aligned.m16n8k16.row.col.f32.bf16.bf16.f32 "
        "{%0,%1,%2,%3}, {%4,%5,%6,%7}, {%8,%9}, {%0,%1,%2,%3};"
        : "+f"(d[0]), "+f"(d[1]), "+f"(d[2]), "+f"(d[3])
        : "r"(a[0]), "r"(a[1]), "r"(a[2]), "r"(a[3]), "r"(b[0]), "r"(b[1]));
}

__device__ __forceinline__ void split_bf16(float f, __nv_bfloat16& hi, __nv_bfloat16& lo) {
    hi = __float2bfloat16(f);
    lo = __float2bfloat16(f - __bfloat162float(hi));
}

// =============================================================================
// Kernels CVT: fp32 -> hi/lo bf16 (device-global targets referenced in device code)
// =============================================================================
__global__ void k_cvtH(const float* __restrict__ X) {
    size_t i = ((size_t)blockIdx.x * 256 + threadIdx.x) * 4;
    float4 v = *(const float4*)(X + i);
    BF4 hi, lo;
    split_bf16(v.x, hi.h[0], lo.h[0]);
    split_bf16(v.y, hi.h[1], lo.h[1]);
    split_bf16(v.z, hi.h[2], lo.h[2]);
    split_bf16(v.w, hi.h[3], lo.h[3]);
    *(uint2*)&g_Hhi[i] = hi.v;
    *(uint2*)&g_Hlo[i] = lo.v;
}
__global__ void k_cvtP(const float* __restrict__ X) {
    size_t i = ((size_t)blockIdx.x * 256 + threadIdx.x) * 4;
    float4 v = *(const float4*)(X + i);
    BF4 hi, lo;
    split_bf16(v.x, hi.h[0], lo.h[0]);
    split_bf16(v.y, hi.h[1], lo.h[1]);
    split_bf16(v.z, hi.h[2], lo.h[2]);
    split_bf16(v.w, hi.h[3], lo.h[3]);
    *(uint2*)&g_Phi[i] = hi.v;
    *(uint2*)&g_Plo[i] = lo.v;
}

// =============================================================================
// Kernel CVTW: W [d][e] -> W^T split bf16 [e][d]
// =============================================================================
__global__ void k_cvtW(const float* __restrict__ W) {
    int idx = blockIdx.x * 256 + threadIdx.x;     // 65536
    int d = idx >> 8, e = idx & 255;
    float v = W[idx];
    __nv_bfloat16 hi, lo;
    split_bf16(v, hi, lo);
    g_Wthi[e * DH + d] = hi;
    g_Wtlo[e * DH + d] = lo;
}

// =============================================================================
// Kernel A (tensor): PW = P @ W  (M=16384, N=256, K=256) split-bf16 3-product
// =============================================================================
__global__ __launch_bounds__(256) void k_pw_mma() {
    __shared__ __align__(16) __nv_bfloat16 Ah[128][40], Al[128][40];
    __shared__ __align__(16) __nv_bfloat16 Bh[128][40], Bl[128][40];
    const int bm = blockIdx.y * 128, bn = blockIdx.x * 128;
    const int tid = threadIdx.x, warp = tid >> 5, lane = tid & 31;
    const int wm = (warp >> 2) * 64, wn = (warp & 3) * 32;
    const int gid = lane >> 2, tig = lane & 3;
    const int lrow = tid >> 1, lseg = (tid & 1) * 16;

    const size_t abase = (size_t)(bm + lrow) * DH + lseg;
    const size_t bbase = (size_t)(bn + lrow) * DH + lseg;

    float acc[4][4][4];
#pragma unroll
    for (int mt = 0; mt < 4; mt++)
#pragma unroll
        for (int nt = 0; nt < 4; nt++)
#pragma unroll
            for (int e = 0; e < 4; e++) acc[mt][nt][e] = 0.0f;

    for (int k0 = 0; k0 < DH; k0 += 32) {
        uint4 ah0 = *(const uint4*)&g_Phi[abase + k0];
        uint4 ah1 = *(const uint4*)&g_Phi[abase + k0 + 8];
        uint4 al0 = *(const uint4*)&g_Plo[abase + k0];
        uint4 al1 = *(const uint4*)&g_Plo[abase + k0 + 8];
        uint4 bh0 = *(const uint4*)&g_Wthi[bbase + k0];
        uint4 bh1 = *(const uint4*)&g_Wthi[bbase + k0 + 8];
        uint4 bl0 = *(const uint4*)&g_Wtlo[bbase + k0];
        uint4 bl1 = *(const uint4*)&g_Wtlo[bbase + k0 + 8];
        __syncthreads();
        *(uint4*)&Ah[lrow][lseg] = ah0; *(uint4*)&Ah[lrow][lseg + 8] = ah1;
        *(uint4*)&Al[lrow][lseg] = al0; *(uint4*)&Al[lrow][lseg + 8] = al1;
        *(uint4*)&Bh[lrow][lseg] = bh0; *(uint4*)&Bh[lrow][lseg + 8] = bh1;
        *(uint4*)&Bl[lrow][lseg] = bl0; *(uint4*)&Bl[lrow][lseg + 8] = bl1;
        __syncthreads();
#pragma unroll
        for (int ks = 0; ks < 32; ks += 16) {
            unsigned afh[4][4], afl[4][4];
#pragma unroll
            for (int mt = 0; mt < 4; mt++) {
                int r = wm + mt * 16 + gid;
                afh[mt][0] = *(const unsigned*)&Ah[r][ks + tig * 2];
                afh[mt][1] = *(const unsigned*)&Ah[r + 8][ks + tig * 2];
                afh[mt][2] = *(const unsigned*)&Ah[r][ks + tig * 2 + 8];
                afh[mt][3] = *(const unsigned*)&Ah[r + 8][ks + tig * 2 + 8];
                afl[mt][0] = *(const unsigned*)&Al[r][ks + tig * 2];
                afl[mt][1] = *(const unsigned*)&Al[r + 8][ks + tig * 2];
                afl[mt][2] = *(const unsigned*)&Al[r][ks + tig * 2 + 8];
                afl[mt][3] = *(const unsigned*)&Al[r + 8][ks + tig * 2 + 8];
            }
#pragma unroll
            for (int nt = 0; nt < 4; nt++) {
                int nr = wn + nt * 8 + gid;
                unsigned bfh[2] = {*(const unsigned*)&Bh[nr][ks + tig * 2],
                                   *(const unsigned*)&Bh[nr][ks + tig * 2 + 8]};
                unsigned bfl[2] = {*(const unsigned*)&Bl[nr][ks + tig * 2],
                                   *(const unsigned*)&Bl[nr][ks + tig * 2 + 8]};
#pragma unroll
                for (int mt = 0; mt < 4; mt++) {
                    mma_bf16(acc[mt][nt], afh[mt], bfh);
                    mma_bf16(acc[mt][nt], afh[mt], bfl);
                    mma_bf16(acc[mt][nt], afl[mt], bfh);
                }
            }
        }
    }
#pragma unroll
    for (int mt = 0; mt < 4; mt++) {
        int r0 = bm + wm + mt * 16 + gid, r1 = r0 + 8;
#pragma unroll
        for (int nt = 0; nt < 4; nt++) {
            int c = bn + wn + nt * 8 + tig * 2;
            float* d = acc[mt][nt];
            BF2 h0, l0, h1, l1;
            split_bf16(d[0], h0.h[0], l0.h[0]);
            split_bf16(d[1], h0.h[1], l0.h[1]);
            split_bf16(d[2], h1.h[0], l1.h[0]);
            split_bf16(d[3], h1.h[1], l1.h[1]);
            *(unsigned*)&g_PWhi[(size_t)r0 * DH + c] = h0.u;
            *(unsigned*)&g_PWlo[(size_t)r0 * DH + c] = l0.u;
            *(unsigned*)&g_PWhi[(size_t)r1 * DH + c] = h1.u;
            *(unsigned*)&g_PWlo[(size_t)r1 * DH + c] = l1.u;
        }
    }
}

// =============================================================================
// Kernel B: sim[b] = PW[b] @ H[b]^T + bias + mask  — tensor-core split-bf16
// =============================================================================
__global__ __launch_bounds__(256) void k_sim(const int* __restrict__ pmask,
                                             const int* __restrict__ hmask,
                                             const float* __restrict__ bias) {
    __shared__ __align__(16) __nv_bfloat16 Ah[128][40], Al[128][40];
    __shared__ __align__(16) __nv_bfloat16 Bh[128][40], Bl[128][40];
    const int b = blockIdx.z;
    const int bm = blockIdx.y * 128, bn = blockIdx.x * 128;
    const int tid = threadIdx.x, warp = tid >> 5, lane = tid & 31;
    const int wm = (warp >> 2) * 64, wn = (warp & 3) * 32;
    const int gid = lane >> 2, tig = lane & 3;
    const int lrow = tid >> 1, lseg = (tid & 1) * 16;

    const size_t abase = ((size_t)b * LL + bm + lrow) * DH + lseg;
    const size_t bbase = ((size_t)b * LL + bn + lrow) * DH + lseg;

    float acc[4][4][4];
#pragma unroll
    for (int mt = 0; mt < 4; mt++)
#pragma unroll
        for (int nt = 0; nt < 4; nt++)
#pragma unroll
            for (int e = 0; e < 4; e++) acc[mt][nt][e] = 0.0f;

    for (int k0 = 0; k0 < DH; k0 += 32) {
        uint4 ah0 = *(const uint4*)&g_PWhi[abase + k0];
        uint4 ah1 = *(const uint4*)&g_PWhi[abase + k0 + 8];
        uint4 al0 = *(const uint4*)&g_PWlo[abase + k0];
        uint4 al1 = *(const uint4*)&g_PWlo[abase + k0 + 8];
        uint4 bh0 = *(const uint4*)&g_Hhi[bbase + k0];
        uint4 bh1 = *(const uint4*)&g_Hhi[bbase + k0 + 8];
        uint4 bl0 = *(const uint4*)&g_Hlo[bbase + k0];
        uint4 bl1 = *(const uint4*)&g_Hlo[bbase + k0 + 8];
        __syncthreads();
        *(uint4*)&Ah[lrow][lseg] = ah0; *(uint4*)&Ah[lrow][lseg + 8] = ah1;
        *(uint4*)&Al[lrow][lseg] = al0; *(uint4*)&Al[lrow][lseg + 8] = al1;
        *(uint4*)&Bh[lrow][lseg] = bh0; *(uint4*)&Bh[lrow][lseg + 8] = bh1;
        *(uint4*)&Bl[lrow][lseg] = bl0; *(uint4*)&Bl[lrow][lseg + 8] = bl1;
        __syncthreads();
#pragma unroll
        for (int ks = 0; ks < 32; ks += 16) {
            unsigned afh[4][4], afl[4][4];
#pragma unroll
            for (int mt = 0; mt < 4; mt++) {
                int r = wm + mt * 16 + gid;
                afh[mt][0] = *(const unsigned*)&Ah[r][ks + tig * 2];
                afh[mt][1] = *(const unsigned*)&Ah[r + 8][ks + tig * 2];
                afh[mt][2] = *(const unsigned*)&Ah[r][ks + tig * 2 + 8];
                afh[mt][3] = *(const unsigned*)&Ah[r + 8][ks + tig * 2 + 8];
                afl[mt][0] = *(const unsigned*)&Al[r][ks + tig * 2];
                afl[mt][1] = *(const unsigned*)&Al[r + 8][ks + tig * 2];
                afl[mt][2] = *(const unsigned*)&Al[r][ks + tig * 2 + 8];
                afl[mt][3] = *(const unsigned*)&Al[r + 8][ks + tig * 2 + 8];
            }
#pragma unroll
            for (int nt = 0; nt < 4; nt++) {
                int nr = wn + nt * 8 + gid;
                unsigned bfh[2] = {*(const unsigned*)&Bh[nr][ks + tig * 2],
                                   *(const unsigned*)&Bh[nr][ks + tig * 2 + 8]};
                unsigned bfl[2] = {*(const unsigned*)&Bl[nr][ks + tig * 2],
                                   *(const unsigned*)&Bl[nr][ks + tig * 2 + 8]};
#pragma unroll
                for (int mt = 0; mt < 4; mt++) {
                    mma_bf16(acc[mt][nt], afh[mt], bfh);
                    mma_bf16(acc[mt][nt], afh[mt], bfl);
                    mma_bf16(acc[mt][nt], afl[mt], bfh);
                }
            }
        }
    }

    const float bb = bias[0];
#pragma unroll
    for (int mt = 0; mt < 4; mt++) {
        int r0 = bm + wm + mt * 16 + gid, r1 = r0 + 8;
        float pm0 = (float)pmask[b * LL + r0];
        float pm1 = (float)pmask[b * LL + r1];
#pragma unroll
        for (int nt = 0; nt < 4; nt++) {
            int c = bn + wn + nt * 8 + tig * 2;
            float hm0 = (float)hmask[b * LL + c];
            float hm1 = (float)hmask[b * LL + c + 1];
            float* d = acc[mt][nt];
            float2 v0 = make_float2(d[0] + bb + (1.0f - pm0 * hm0) * NEGINF,
                                    d[1] + bb + (1.0f - pm0 * hm1) * NEGINF);
            float2 v1 = make_float2(d[2] + bb + (1.0f - pm1 * hm0) * NEGINF,
                                    d[3] + bb + (1.0f - pm1 * hm1) * NEGINF);
            *(float2*)&g_sim[((size_t)b * LL + r0) * LL + c] = v0;
            *(float2*)&g_sim[((size_t)b * LL + r1) * LL + c] = v1;
        }
    }
}

// =============================================================================
// Kernel C (fused): rowmax/rowinv + colmax partials in ONE pass over sim
// =============================================================================
__global__ __launch_bounds__(256) void k_stats() {
    const int blk = blockIdx.x;                    // 0..127
    const int warp = threadIdx.x >> 5, lane = threadIdx.x & 31;
    const int rowbase = blk * 128 + warp * 16;
    const int b = blk >> 3;

    float4 cm[8];
#pragma unroll
    for (int s = 0; s < 8; s++) cm[s] = make_float4(FLT_LOW, FLT_LOW, FLT_LOW, FLT_LOW);

    for (int r = 0; r < 16; r++) {
        const int row = rowbase + r;
        const float* s = g_sim + (size_t)row * LL + lane * 4;
        float4 v[8];
#pragma unroll
        for (int sg = 0; sg < 8; sg++) v[sg] = *(const float4*)(s + sg * 128);
        float m = FLT_LOW;
#pragma unroll
        for (int sg = 0; sg < 8; sg++) {
            m = fmaxf(m, fmaxf(fmaxf(v[sg].x, v[sg].y), fmaxf(v[sg].z, v[sg].w)));
            cm[sg].x = fmaxf(cm[sg].x, v[sg].x);
            cm[sg].y = fmaxf(cm[sg].y, v[sg].y);
            cm[sg].z = fmaxf(cm[sg].z, v[sg].z);
            cm[sg].w = fmaxf(cm[sg].w, v[sg].w);
        }
#pragma unroll
        for (int o = 16; o > 0; o >>= 1) m = fmaxf(m, __shfl_xor_sync(0xffffffffu, m, o));
        float sum = 0.0f;
#pragma unroll
        for (int sg = 0; sg < 8; sg++)
            sum += __expf(v[sg].x - m) + __expf(v[sg].y - m)
                 + __expf(v[sg].z - m) + __expf(v[sg].w - m);
#pragma unroll
        for (int o = 16; o > 0; o >>= 1) sum += __shfl_xor_sync(0xffffffffu, sum, o);
        if (lane == 0) {
            g_rowmax[row] = m;
            g_rowinv[row] = 1.0f / sum;
        }
    }
    const int chunk = (blk & 7) * 8 + warp;        // 0..63 within batch
    float* cp = g_colpart + ((size_t)b * 64 + chunk) * LL + lane * 4;
#pragma unroll
    for (int sg = 0; sg < 8; sg++) *(float4*)(cp + sg * 128) = cm[sg];
}

// =============================================================================
// Kernel D: aligned_hyp[b] = softmax(sim[b]) @ H[b] — tensor-core split-bf16
// =============================================================================
__global__ __launch_bounds__(256) void k_av(float* __restrict__ out) {
    __shared__ __align__(16) __nv_bfloat16 Ah[128][40], Al[128][40];
    __shared__ __align__(16) __nv_bfloat16 Bh[128][40], Bl[128][40];
    const int b = blockIdx.z;
    const int bm = blockIdx.y * 128, bn = blockIdx.x * 128;   // bn over DH
    const int tid = threadIdx.x, warp = tid >> 5, lane = tid & 31;
    const int wm = (warp >> 2) * 64, wn = (warp & 3) * 32;
    const int gid = lane >> 2, tig = lane & 3;
    const int lrow = tid >> 1, lseg = (tid & 1) * 16;
    const int qloc = tid & 31, dbase = (tid >> 5) * 16;

    const float rm = g_rowmax[b * LL + bm + lrow];
    const float ri = g_rowinv[b * LL + bm + lrow];
    const float* sp = &g_sim[((size_t)b * LL + bm + lrow) * LL + lseg];

    float acc[4][4][4];
#pragma unroll
    for (int mt = 0; mt < 4; mt++)
#pragma unroll
        for (int nt = 0; nt < 4; nt++)
#pragma unroll
            for (int e = 0; e < 4; e++) acc[mt][nt][e] = 0.0f;

    for (int k0 = 0; k0 < LL; k0 += 32) {
        float4 f0 = *(const float4*)(sp + k0);
        float4 f1 = *(const float4*)(sp + k0 + 4);
        float4 f2 = *(const float4*)(sp + k0 + 8);
        float4 f3 = *(const float4*)(sp + k0 + 12);
        size_t hb = ((size_t)b * LL + k0 + qloc) * DH + bn + dbase;
        BF8 hh0 = *(const BF8*)&g_Hhi[hb];
        BF8 hh1 = *(const BF8*)&g_Hhi[hb + 8];
        BF8 hl0 = *(const BF8*)&g_Hlo[hb];
        BF8 hl1 = *(const BF8*)&g_Hlo[hb + 8];
        __syncthreads();
        {
            float e[16] = {f0.x, f0.y, f0.z, f0.w, f1.x, f1.y, f1.z, f1.w,
                           f2.x, f2.y, f2.z, f2.w, f3.x, f3.y, f3.z, f3.w};
            BF8 phi0, phi1, plo0, plo1;
#pragma unroll
            for (int i = 0; i < 8; i++) {
                float p0 = __expf(e[i] - rm) * ri;
                float p1 = __expf(e[8 + i] - rm) * ri;
                split_bf16(p0, phi0.h[i], plo0.h[i]);
                split_bf16(p1, phi1.h[i], plo1.h[i]);
            }
            *(uint4*)&Ah[lrow][lseg] = phi0.v; *(uint4*)&Ah[lrow][lseg + 8] = phi1.v;
            *(uint4*)&Al[lrow][lseg] = plo0.v; *(uint4*)&Al[lrow][lseg + 8] = plo1.v;
        }
#pragma unroll
        for (int i = 0; i < 8; i++) {
            Bh[dbase + i][qloc] = hh0.h[i];
            Bh[dbase + 8 + i][qloc] = hh1.h[i];
            Bl[dbase + i][qloc] = hl0.h[i];
            Bl[dbase + 8 + i][qloc] = hl1.h[i];
        }
        __syncthreads();
#pragma unroll
        for (int ks = 0; ks < 32; ks += 16) {
            unsigned afh[4][4], afl[4][4];
#pragma unroll
            for (int mt = 0; mt < 4; mt++) {
                int r = wm + mt * 16 + gid;
                afh[mt][0] = *(const unsigned*)&Ah[r][ks + tig * 2];
                afh[mt][1] = *(const unsigned*)&Ah[r + 8][ks + tig * 2];
                afh[mt][2] = *(const unsigned*)&Ah[r][ks + tig * 2 + 8];
                afh[mt][3] = *(const unsigned*)&Ah[r + 8][ks + tig * 2 + 8];
                afl[mt][0] = *(const unsigned*)&Al[r][ks + tig * 2];
                afl[mt][1] = *(const unsigned*)&Al[r + 8][ks + tig * 2];
                afl[mt][2] = *(const unsigned*)&Al[r][ks + tig * 2 + 8];
                afl[mt][3] = *(const unsigned*)&Al[r + 8][ks + tig * 2 + 8];
            }
#pragma unroll
            for (int nt = 0; nt < 4; nt++) {
                int nr = wn + nt * 8 + gid;
                unsigned bfh[2] = {*(const unsigned*)&Bh[nr][ks + tig * 2],
                                   *(const unsigned*)&Bh[nr][ks + tig * 2 + 8]};
                unsigned bfl[2] = {*(const unsigned*)&Bl[nr][ks + tig * 2],
                                   *(const unsigned*)&Bl[nr][ks + tig * 2 + 8]};
#pragma unroll
                for (int mt = 0; mt < 4; mt++) {
                    mma_bf16(acc[mt][nt], afh[mt], bfh);
                    mma_bf16(acc[mt][nt], afh[mt], bfl);
                    mma_bf16(acc[mt][nt], afl[mt], bfh);
                }
            }
        }
    }
#pragma unroll
    for (int mt = 0; mt < 4; mt++) {
        int r0 = bm + wm + mt * 16 + gid, r1 = r0 + 8;
#pragma unroll
        for (int nt = 0; nt < 4; nt++) {
            int c = bn + wn + nt * 8 + tig * 2;
            float* d = acc[mt][nt];
            *(float2*)&out[((size_t)b * LL + r0) * DH + c] = make_float2(d[0], d[1]);
            *(float2*)&out[((size_t)b * LL + r1) * DH + c] = make_float2(d[2], d[3]);
        }
    }
}

// =============================================================================
// Kernel E: per batch — softmax(colmax over 64 partials) @ P -> g_pvec
// =============================================================================
__global__ __launch_bounds__(256) void k_premise(const float* __restrict__ P) {
    const int b = blockIdx.x;
    const int t = threadIdx.x;
    __shared__ float prob[LL];
    __shared__ float red[8];
    float loc[4];
#pragma unroll
    for (int c = 0; c < 4; c++) {
        int q = c * 256 + t;
        float m = FLT_LOW;
        for (int j = 0; j < 64; j++)
            m = fmaxf(m, g_colpart[((size_t)b * 64 + j) * LL + q]);
        loc[c] = m;
    }
    float mx = fmaxf(fmaxf(loc[0], loc[1]), fmaxf(loc[2], loc[3]));
#pragma unroll
    for (int o = 16; o > 0; o >>= 1) mx = fmaxf(mx, __shfl_xor_sync(0xffffffffu, mx, o));
    const int w = t >> 5, lane = t & 31;
    if (lane == 0) red[w] = mx;
    __syncthreads();
    mx = red[0];
#pragma unroll
    for (int j = 1; j < 8; j++) mx = fmaxf(mx, red[j]);

    float se = 0.0f;
#pragma unroll
    for (int c = 0; c < 4; c++) {
        float e = __expf(loc[c] - mx);
        prob[c * 256 + t] = e;
        se += e;
    }
#pragma unroll
    for (int o = 16; o > 0; o >>= 1) se += __shfl_xor_sync(0xffffffffu, se, o);
    __syncthreads();
    if (lane == 0) red[w] = se;
    __syncthreads();
    float tot = 0.0f;
#pragma unroll
    for (int j = 0; j < 8; j++) tot += red[j];
    const float inv = 1.0f / tot;

    const float* Pb = P + (size_t)b * LL * DH + t;
    float acc = 0.0f;
#pragma unroll 8
    for (int q = 0; q < LL; q++)
        acc = fmaf(prob[q], Pb[(size_t)q * DH], acc);
    g_pvec[b * DH + t] = acc * inv;
}

// =============================================================================
// Kernel F: broadcast g_pvec -> out[0 : NB*LL*DH)
// =============================================================================
__global__ void k_bcast(float* __restrict__ out) {
    int idx = (blockIdx.x * 256 + threadIdx.x) * 4;
    int b = idx >> 18;
    int d = idx & (DH - 1);
    float4 v = *(const float4*)&g_pvec[b * DH + d];
    *(float4*)&out[idx] = v;
}

// =============================================================================
extern "C" void kernel_launch(void* const* d_in, const int* in_sizes, int n_in,
                              void* d_out, int out_size) {
    const float* P    = (const float*)d_in[0];
    const float* Hh   = (const float*)d_in[1];
    const int*   pm   = (const int*)d_in[2];
    const int*   hm   = (const int*)d_in[3];
    const float* W    = (const float*)d_in[4];
    const float* bias = (const float*)d_in[5];
    float* out = (float*)d_out;

    k_cvtH    <<<(NB * LL * DH) / (256 * 4), 256>>>(Hh);
    k_cvtP    <<<(NB * LL * DH) / (256 * 4), 256>>>(P);
    k_cvtW    <<<DH * DH / 256, 256>>>(W);
    k_pw_mma  <<<dim3(DH / 128, (NB * LL) / 128), 256>>>();
    k_sim     <<<dim3(LL / 128, LL / 128, NB), 256>>>(pm, hm, bias);
    k_stats   <<<(NB * LL) / 128, 256>>>();
    k_av      <<<dim3(DH / 128, LL / 128, NB), 256>>>(out + (size_t)NB * LL * DH);
    k_premise <<<NB, 256>>>(P);
    k_bcast   <<<(NB * LL * DH) / (256 * 4), 256>>>(out);
}